// round 11
// baseline (speedup 1.0000x reference)
#include <cuda_runtime.h>
#include <cuda_fp16.h>
#include <cstdint>

// ============================================================
// DST-II y[16384,1024] via Cooley-Tukey split n = 32a + b:
//  Stage1: P/Q[rp][b] = sum_a x[32a+b] * {sin,cos}(pi a rp/32), rp in [0,32]
//  Stage2 (residue form): R = ((m-1) mod 64)+1, rp = min(R,64-R):
//    y[64c + R] = P[rp]*(sgnP cosB) + Q[rp]*sinB
// R11: 8 signals / 128 threads / CTA, 54.8KB smem -> 4 CTAs/SM.
//      Stage-2 A = 8 rows via dup-row MMA (ldsm.x4 k-octet addressing).
// ============================================================

#define BATCH   16384
#define SIGS    8
#define THREADS 128
#define PQ_PITCH 1040

// smem layout (bytes)
#define SM_X    0          // x: [s8][a32][b32] fp16 pitch 80 = 20480 B; later y-staging fp16 [s8][128 chunks x16B]
#define SM_PQ   20480      // [rp33]{[s8] rows of 128B, XOR-chunk swizzle}, pitch 1040
#define SMEM_TOTAL (SM_PQ + 33 * PQ_PITCH)   // 54800

// gmem scratch (pre-packed mma fragments)
__device__ uint4 g_Wf[4 * 2 * 32];      // [mi4][ks2][lane32] A-fragments of compacted W
__device__ uint4 g_B2n[64 * 4 * 32];    // [R-1][nj*2+ksh][lane32] B-fragments

// ---------------- helpers ----------------
__device__ __forceinline__ uint32_t smem_u32(const void* p) {
    uint32_t a;
    asm("{ .reg .u64 t; cvta.to.shared.u64 t, %1; cvt.u32.u64 %0, t; }" : "=r"(a) : "l"(p));
    return a;
}
__device__ __forceinline__ void ldm_x4(uint32_t* r, uint32_t addr) {
    asm volatile("ldmatrix.sync.aligned.m8n8.x4.shared.b16 {%0,%1,%2,%3}, [%4];\n"
                 : "=r"(r[0]), "=r"(r[1]), "=r"(r[2]), "=r"(r[3]) : "r"(addr));
}
__device__ __forceinline__ void ldm_x4_t(uint32_t* r, uint32_t addr) {
    asm volatile("ldmatrix.sync.aligned.m8n8.x4.trans.shared.b16 {%0,%1,%2,%3}, [%4];\n"
                 : "=r"(r[0]), "=r"(r[1]), "=r"(r[2]), "=r"(r[3]) : "r"(addr));
}
__device__ __forceinline__ void mma_16816(float* c, const uint32_t* a, const uint32_t* b) {
    asm volatile(
        "mma.sync.aligned.m16n8k16.row.col.f32.f16.f16.f32 "
        "{%0,%1,%2,%3}, {%4,%5,%6,%7}, {%8,%9}, {%0,%1,%2,%3};\n"
        : "+f"(c[0]), "+f"(c[1]), "+f"(c[2]), "+f"(c[3])
        : "r"(a[0]), "r"(a[1]), "r"(a[2]), "r"(a[3]), "r"(b[0]), "r"(b[1]));
}
__device__ __forceinline__ void sts32(uint32_t addr, uint32_t v) {
    asm volatile("st.shared.b32 [%0], %1;\n" :: "r"(addr), "r"(v));
}
__device__ __forceinline__ void sts128(uint32_t addr, uint32_t a, uint32_t b,
                                       uint32_t c, uint32_t d) {
    asm volatile("st.shared.v4.b32 [%0], {%1,%2,%3,%4};\n"
                 :: "r"(addr), "r"(a), "r"(b), "r"(c), "r"(d));
}
__device__ __forceinline__ void lds64(uint32_t addr, uint32_t& lo, uint32_t& hi) {
    asm volatile("ld.shared.v2.b32 {%0,%1}, [%2];\n" : "=r"(lo), "=r"(hi) : "r"(addr));
}
__device__ __forceinline__ uint32_t pk2(float a, float b) {
    __half2 h = __floats2half2_rn(a, b);
    return *reinterpret_cast<uint32_t*>(&h);
}

// ============================================================
// Basis values
// ============================================================
__device__ __forceinline__ float w_val(int f, int a) {  // f = 2rp+pq
    int rp = f >> 1, pq = f & 1;
    if (rp > 32) return 0.0f;
    int mm = pq ? ((a * rp + 16) & 63) : ((a * rp) & 63);
    return sinpif((float)mm * (1.0f / 32.0f));
}
// compacted W row fp (0..63): fp<63 -> f=fp+1; fp=63 -> f=65 (Q[32])
__device__ __forceinline__ float w2_val(int fp, int a) {
    int f = (fp == 63) ? 65 : fp + 1;
    return w_val(f, a);
}
// stage-2 residue basis: R in 1..64, col in 0..15, q = pq*32 + b
__device__ __forceinline__ float b2n_val(int r, int col, int q) {
    int m = 64 * col + r;
    int b = q & 31, pq = q >> 5;
    int ang = ((2 * b + 1) * m) & 4095;
    if (pq == 0) {
        if (r == 32 || r == 64) return 0.0f;   // P[32]=P[0]=0
        float sgn = (r <= 32) ? 1.0f : -1.0f;
        return sgn * sinpif((float)((ang + 1024) & 4095) * (1.0f / 2048.0f));
    }
    return sinpif((float)ang * (1.0f / 2048.0f));
}

__global__ void build_basis_kernel() {
    int bid = blockIdx.x;
    int tid = threadIdx.x;
    if (bid == 0) {
        if (tid < 256) {
            int mi = tid >> 6, ks = (tid >> 5) & 1, l = tid & 31;
            int r0 = l >> 2, k0 = 16 * ks + 2 * (l & 3);
            uint4 o;
            o.x = pk2(w2_val(mi * 16 + r0,     k0),     w2_val(mi * 16 + r0,     k0 + 1));
            o.y = pk2(w2_val(mi * 16 + 8 + r0, k0),     w2_val(mi * 16 + 8 + r0, k0 + 1));
            o.z = pk2(w2_val(mi * 16 + r0,     k0 + 8), w2_val(mi * 16 + r0,     k0 + 9));
            o.w = pk2(w2_val(mi * 16 + 8 + r0, k0 + 8), w2_val(mi * 16 + 8 + r0, k0 + 9));
            g_Wf[(mi * 2 + ks) * 32 + l] = o;
        }
    } else {
        int r = bid;   // residue 1..64
        if (tid < 128) {
            int f2 = tid >> 5, t = tid & 31;
            int nj = f2 >> 1, ksh = f2 & 1;
            int col = nj * 8 + (t >> 2);
            int q0 = (2 * ksh) * 16 + 2 * (t & 3);
            int q1 = q0 + 16;
            uint4 o;
            o.x = pk2(b2n_val(r, col, q0),     b2n_val(r, col, q0 + 1));
            o.y = pk2(b2n_val(r, col, q0 + 8), b2n_val(r, col, q0 + 9));
            o.z = pk2(b2n_val(r, col, q1),     b2n_val(r, col, q1 + 1));
            o.w = pk2(b2n_val(r, col, q1 + 8), b2n_val(r, col, q1 + 9));
            g_B2n[(r - 1) * 128 + f2 * 32 + t] = o;
        }
    }
}

// ============================================================
// Main fused kernel: 8 signals / CTA, 128 threads (4 warps), 4 CTAs/SM.
// ============================================================
__global__ void __launch_bounds__(THREADS, 4)
dst_fused_kernel(const float* __restrict__ x, float* __restrict__ y) {
    extern __shared__ char smem[];
    const uint32_t sb = smem_u32(smem);
    const int tid  = threadIdx.x;
    const int wid  = tid >> 5;          // 0..3
    const int lane = tid & 31;
    const int jj   = lane >> 3;
    const int ri   = lane & 7;
    const size_t s_base = (size_t)blockIdx.x * SIGS;

    // ---- W A-fragments -> regs (L2-hot ldg, overlaps x loads) ----
    uint4 Wf[8];
    {
        const uint4* p = g_Wf + lane;
        #pragma unroll
        for (int f = 0; f < 8; f++) Wf[f] = __ldg(p + f * 32);
    }

    // ---- per-warp x load: signals 2wid, 2wid+1 (fp32 -> fp16, pitch 80) ----
    #pragma unroll
    for (int ss = 0; ss < 2; ss++) {
        const int s = 2 * wid + ss;
        const float4* xs = reinterpret_cast<const float4*>(x + (s_base + s) * 1024);
        float4 xv[8];
        #pragma unroll
        for (int i = 0; i < 8; i++) xv[i] = xs[i * 32 + lane];
        #pragma unroll
        for (int i = 0; i < 8; i++) {
            int a = 4 * i + (lane >> 3), b = 4 * (lane & 7);
            uint2 pk;
            pk.x = pk2(xv[i].x, xv[i].y);
            pk.y = pk2(xv[i].z, xv[i].w);
            *reinterpret_cast<uint2*>(smem + SM_X + s * 2560 + a * 80 + b * 2) = pk;
        }
    }

    // ---- zero P-halves of PQ rows rp=0 and rp=32 for own signals ----
    {
        int L = lane & 15;
        int s = 2 * wid + (lane >> 4);
        uint32_t off = (uint32_t)(s * 128 + (((L >> 2) ^ (s & 7)) << 4) + 4 * (L & 3));
        sts32(sb + SM_PQ + off, 0u);                     // rp = 0
        sts32(sb + SM_PQ + 32 * PQ_PITCH + off, 0u);     // rp = 32
    }

    __syncwarp();   // own x rows + zeros visible to this warp

    // ================= Stage 1: warp = 2 signals, 4 mi tiles =================
    const int g = lane >> 2, t4 = lane & 3;
    #pragma unroll
    for (int ss = 0; ss < 2; ss++) {
        const int s = 2 * wid + ss;
        uint32_t bf[2][4][2];
        #pragma unroll
        for (int ks = 0; ks < 2; ks++)
            #pragma unroll
            for (int n16 = 0; n16 < 2; n16++) {
                int a = ks * 16 + (lane & 15);
                uint32_t addr = sb + SM_X + (uint32_t)(s * 2560 + a * 80
                              + (n16 * 16 + (lane >> 4) * 8) * 2);
                uint32_t t[4];
                ldm_x4_t(t, addr);
                bf[ks][n16 * 2 + 0][0] = t[0]; bf[ks][n16 * 2 + 0][1] = t[1];
                bf[ks][n16 * 2 + 1][0] = t[2]; bf[ks][n16 * 2 + 1][1] = t[3];
            }
        #pragma unroll
        for (int mi = 0; mi < 4; mi++) {
            float acc[4][4];
            #pragma unroll
            for (int n8 = 0; n8 < 4; n8++)
                #pragma unroll
                for (int q = 0; q < 4; q++) acc[n8][q] = 0.0f;
            #pragma unroll
            for (int ks = 0; ks < 2; ks++) {
                uint32_t af[4] = { Wf[mi * 2 + ks].x, Wf[mi * 2 + ks].y,
                                   Wf[mi * 2 + ks].z, Wf[mi * 2 + ks].w };
                #pragma unroll
                for (int n8 = 0; n8 < 4; n8++)
                    mma_16816(acc[n8], af, bf[ks][n8]);
            }
            // unpredicated packed scatter: fp -> f = (fp==63)?65:fp+1
            #pragma unroll
            for (int n8 = 0; n8 < 4; n8++)
                #pragma unroll
                for (int ch = 0; ch < 2; ch++) {
                    int fp = mi * 16 + g + (ch << 3);
                    int f  = (fp == 63) ? 65 : fp + 1;
                    int b  = n8 * 8 + 2 * t4;        // even
                    int rp = f >> 1, pq = f & 1;
                    int u  = pq * 64 + 2 * b;        // byte offset, 4-aligned
                    uint32_t addr = sb + SM_PQ + (uint32_t)(rp * PQ_PITCH + s * 128
                                  + (((u >> 4) ^ (s & 7)) << 4) + (u & 15));
                    sts32(addr, pk2(acc[n8][2 * ch], acc[n8][2 * ch + 1]));
                }
        }
    }

    // prefetch first residue's B fragments (independent of PQ barrier)
    uint4 Bc[2][2];
    {
        const uint4* p = g_B2n + (size_t)(16 * wid) * 128 + lane;
        Bc[0][0] = __ldg(p);      Bc[0][1] = __ldg(p + 32);
        Bc[1][0] = __ldg(p + 64); Bc[1][1] = __ldg(p + 96);
    }

    __syncthreads();   // PQ complete; x buffer dead -> y staging (fp16 chunks)

    // ================= Stage 2: residues R = 16*wid+1 .. 16*wid+16 =================
    // dup-row A: ldsm.x4 gathers 4 k-octets of the 8 valid signal rows; MMA A
    // operand duplicates each octet into rows 8-15 (outputs there ignored).
    #pragma unroll
    for (int rr = 0; rr < 2; rr++) {
        uint32_t u0[4][2], u1[4][2];   // [nj*2+cc][lohi]
        #pragma unroll
        for (int h = 0; h < 2; h++) {
            float acc[4][2][4];
            #pragma unroll
            for (int e = 0; e < 4; e++)
                #pragma unroll
                for (int nj = 0; nj < 2; nj++)
                    #pragma unroll
                    for (int q = 0; q < 4; q++) acc[e][nj][q] = 0.0f;

            #pragma unroll
            for (int e = 0; e < 4; e++) {
                int idx = rr * 8 + h * 4 + e;        // 0..15
                int R   = 16 * wid + idx + 1;
                int rp  = (R <= 32) ? R : 64 - R;

                // A: 8 rows x k64 via 2 ldsm.x4 (k-octet per jj)
                uint32_t abase = sb + SM_PQ + (uint32_t)(rp * PQ_PITCH + ri * 128);
                uint32_t tA[4], tB[4];
                ldm_x4(tA, abase + (uint32_t)((jj ^ ri) << 4));
                ldm_x4(tB, abase + (uint32_t)(((jj + 4) ^ ri) << 4));

                // prefetch next residue's B
                uint4 Bn[2][2];
                if (idx < 15) {
                    const uint4* p = g_B2n + (size_t)(16 * wid + idx + 1) * 128 + lane;
                    Bn[0][0] = __ldg(p);      Bn[0][1] = __ldg(p + 32);
                    Bn[1][0] = __ldg(p + 64); Bn[1][1] = __ldg(p + 96);
                }

                #pragma unroll
                for (int nj = 0; nj < 2; nj++) {
                    uint32_t a0[4] = { tA[0], tA[0], tA[1], tA[1] };
                    uint32_t b0[2] = { Bc[nj][0].x, Bc[nj][0].y };
                    mma_16816(acc[e][nj], a0, b0);
                    uint32_t a1[4] = { tA[2], tA[2], tA[3], tA[3] };
                    uint32_t b1[2] = { Bc[nj][0].z, Bc[nj][0].w };
                    mma_16816(acc[e][nj], a1, b1);
                    uint32_t a2[4] = { tB[0], tB[0], tB[1], tB[1] };
                    uint32_t b2[2] = { Bc[nj][1].x, Bc[nj][1].y };
                    mma_16816(acc[e][nj], a2, b2);
                    uint32_t a3[4] = { tB[2], tB[2], tB[3], tB[3] };
                    uint32_t b3[2] = { Bc[nj][1].z, Bc[nj][1].w };
                    mma_16816(acc[e][nj], a3, b3);
                }
                if (idx < 15) {
                    #pragma unroll
                    for (int nj = 0; nj < 2; nj++)
                        #pragma unroll
                        for (int kk = 0; kk < 2; kk++) Bc[nj][kk] = Bn[nj][kk];
                }
            }

            // pack: lane (nj, cc in {0,1}) covers m = 64col + 16wid + 8rr + 4h + e
            #pragma unroll
            for (int nj = 0; nj < 2; nj++)
                #pragma unroll
                for (int cc = 0; cc < 2; cc++) {
                    uint32_t lo = pk2(acc[0][nj][cc], acc[1][nj][cc]);
                    uint32_t hi = pk2(acc[2][nj][cc], acc[3][nj][cc]);
                    if (h == 0) { u0[nj * 2 + cc][0] = lo; u0[nj * 2 + cc][1] = hi; }
                    else        { u1[nj * 2 + cc][0] = lo; u1[nj * 2 + cc][1] = hi; }
                }
        }

        // store staged chunks: chunk L = 8col + 2wid + rr, phys = L ^ (s&7)
        #pragma unroll
        for (int nj = 0; nj < 2; nj++)
            #pragma unroll
            for (int cc = 0; cc < 2; cc++) {
                int col = nj * 8 + 2 * t4 + cc;
                int s   = g;                       // rows 0..7 valid only
                uint32_t L = (uint32_t)(8 * col + 2 * wid + rr);
                uint32_t phys = L ^ (uint32_t)(s & 7);
                sts128(sb + SM_X + (uint32_t)(s * 2048) + phys * 16,
                       u0[nj * 2 + cc][0], u0[nj * 2 + cc][1],
                       u1[nj * 2 + cc][0], u1[nj * 2 + cc][1]);
            }
    }

    __syncthreads();

    // ---- copy-out: fp16 staging -> fp32 gmem, fully coalesced ----
    #pragma unroll
    for (int i = 0; i < 16; i++) {
        int flat = i * THREADS + tid;           // 0..2047 float4 index
        int s  = flat >> 8;
        int f4 = flat & 255;
        uint32_t L = (uint32_t)(f4 >> 1);
        uint32_t half = (uint32_t)(f4 & 1);
        uint32_t phys = L ^ (uint32_t)(s & 7);
        uint32_t lo, hi;
        lds64(sb + SM_X + (uint32_t)(s * 2048) + phys * 16 + half * 8, lo, hi);
        __half2 hl = *reinterpret_cast<__half2*>(&lo);
        __half2 hh = *reinterpret_cast<__half2*>(&hi);
        float2 f0 = __half22float2(hl);
        float2 f1 = __half22float2(hh);
        float4 v = make_float4(f0.x, f0.y, f1.x, f1.y);
        *reinterpret_cast<float4*>(y + (s_base + s) * 1024 + f4 * 4) = v;
    }
}

// ============================================================
// Launch
// ============================================================
extern "C" void kernel_launch(void* const* d_in, const int* in_sizes, int n_in,
                              void* d_out, int out_size) {
    const float* x = (const float*)d_in[0];
    float* y = (float*)d_out;

    build_basis_kernel<<<65, 512>>>();

    cudaFuncSetAttribute(dst_fused_kernel,
                         cudaFuncAttributeMaxDynamicSharedMemorySize, SMEM_TOTAL);
    dst_fused_kernel<<<BATCH / SIGS, THREADS, SMEM_TOTAL>>>(x, y);
}

// round 12
// speedup vs baseline: 1.0696x; 1.0696x over previous
#include <cuda_runtime.h>
#include <cuda_fp16.h>
#include <cstdint>

// ============================================================
// DST-II y[16384,1024] via Cooley-Tukey split n = 32a + b:
//  Stage1: P/Q[rp][b] = sum_a x[32a+b] * {sin,cos}(pi a rp/32), rp in [0,32]
//  Stage2 flipped: y^T[m=64c+R, s] = B2[R][c][q] * PQ^T[q][s]
//    A = basis (m16 = 16 c-values), B = PQ^T (n8 = 8 signals), k = q64.
// R12: 8 signals / 128 threads / CTA, 4 CTAs/SM, no dup-row waste.
// ============================================================

#define BATCH   16384
#define SIGS    8
#define THREADS 128
#define PQ_PITCH 1040

// smem layout (bytes)
#define SM_X    0          // x: [s8][a32][b32] fp16 pitch 80 = 20480 B; later y-staging fp16 [s8][128 chunks x16B]
#define SM_PQ   20480      // [rp33]{[s8] rows of 128B, XOR-chunk swizzle}, pitch 1040
#define SMEM_TOTAL (SM_PQ + 33 * PQ_PITCH)   // 54800

// gmem scratch (pre-packed mma fragments)
__device__ uint4 g_Wf[4 * 2 * 32];      // [mi4][ks2][lane32] A-fragments of compacted W
__device__ uint4 g_B2a[64 * 4 * 32];    // [R-1][ks4][lane32] A-fragments of stage-2 basis

// ---------------- helpers ----------------
__device__ __forceinline__ uint32_t smem_u32(const void* p) {
    uint32_t a;
    asm("{ .reg .u64 t; cvta.to.shared.u64 t, %1; cvt.u32.u64 %0, t; }" : "=r"(a) : "l"(p));
    return a;
}
__device__ __forceinline__ void ldm_x4(uint32_t* r, uint32_t addr) {
    asm volatile("ldmatrix.sync.aligned.m8n8.x4.shared.b16 {%0,%1,%2,%3}, [%4];\n"
                 : "=r"(r[0]), "=r"(r[1]), "=r"(r[2]), "=r"(r[3]) : "r"(addr));
}
__device__ __forceinline__ void ldm_x4_t(uint32_t* r, uint32_t addr) {
    asm volatile("ldmatrix.sync.aligned.m8n8.x4.trans.shared.b16 {%0,%1,%2,%3}, [%4];\n"
                 : "=r"(r[0]), "=r"(r[1]), "=r"(r[2]), "=r"(r[3]) : "r"(addr));
}
__device__ __forceinline__ void mma_16816(float* c, const uint32_t* a, const uint32_t* b) {
    asm volatile(
        "mma.sync.aligned.m16n8k16.row.col.f32.f16.f16.f32 "
        "{%0,%1,%2,%3}, {%4,%5,%6,%7}, {%8,%9}, {%0,%1,%2,%3};\n"
        : "+f"(c[0]), "+f"(c[1]), "+f"(c[2]), "+f"(c[3])
        : "r"(a[0]), "r"(a[1]), "r"(a[2]), "r"(a[3]), "r"(b[0]), "r"(b[1]));
}
__device__ __forceinline__ void sts32(uint32_t addr, uint32_t v) {
    asm volatile("st.shared.b32 [%0], %1;\n" :: "r"(addr), "r"(v));
}
__device__ __forceinline__ void sts128(uint32_t addr, uint32_t a, uint32_t b,
                                       uint32_t c, uint32_t d) {
    asm volatile("st.shared.v4.b32 [%0], {%1,%2,%3,%4};\n"
                 :: "r"(addr), "r"(a), "r"(b), "r"(c), "r"(d));
}
__device__ __forceinline__ void lds64(uint32_t addr, uint32_t& lo, uint32_t& hi) {
    asm volatile("ld.shared.v2.b32 {%0,%1}, [%2];\n" : "=r"(lo), "=r"(hi) : "r"(addr));
}
__device__ __forceinline__ uint32_t pk2(float a, float b) {
    __half2 h = __floats2half2_rn(a, b);
    return *reinterpret_cast<uint32_t*>(&h);
}

// ============================================================
// Basis values
// ============================================================
__device__ __forceinline__ float w_val(int f, int a) {  // f = 2rp+pq
    int rp = f >> 1, pq = f & 1;
    if (rp > 32) return 0.0f;
    int mm = pq ? ((a * rp + 16) & 63) : ((a * rp) & 63);
    return sinpif((float)mm * (1.0f / 32.0f));
}
// compacted W row fp (0..63): fp<63 -> f=fp+1; fp=63 -> f=65 (Q[32])
__device__ __forceinline__ float w2_val(int fp, int a) {
    int f = (fp == 63) ? 65 : fp + 1;
    return w_val(f, a);
}
// stage-2 residue basis: R in 1..64, col in 0..15, q = pq*32 + b
__device__ __forceinline__ float b2n_val(int r, int col, int q) {
    int m = 64 * col + r;
    int b = q & 31, pq = q >> 5;
    int ang = ((2 * b + 1) * m) & 4095;
    if (pq == 0) {
        if (r == 32 || r == 64) return 0.0f;   // P[32]=P[0]=0
        float sgn = (r <= 32) ? 1.0f : -1.0f;
        return sgn * sinpif((float)((ang + 1024) & 4095) * (1.0f / 2048.0f));
    }
    return sinpif((float)ang * (1.0f / 2048.0f));
}

__global__ void build_basis_kernel() {
    int bid = blockIdx.x;
    int tid = threadIdx.x;
    if (bid == 0) {
        if (tid < 256) {
            int mi = tid >> 6, ks = (tid >> 5) & 1, l = tid & 31;
            int r0 = l >> 2, k0 = 16 * ks + 2 * (l & 3);
            uint4 o;
            o.x = pk2(w2_val(mi * 16 + r0,     k0),     w2_val(mi * 16 + r0,     k0 + 1));
            o.y = pk2(w2_val(mi * 16 + 8 + r0, k0),     w2_val(mi * 16 + 8 + r0, k0 + 1));
            o.z = pk2(w2_val(mi * 16 + r0,     k0 + 8), w2_val(mi * 16 + r0,     k0 + 9));
            o.w = pk2(w2_val(mi * 16 + 8 + r0, k0 + 8), w2_val(mi * 16 + 8 + r0, k0 + 9));
            g_Wf[(mi * 2 + ks) * 32 + l] = o;
        }
    } else {
        int R = bid;   // residue 1..64
        if (tid < 128) {
            int ks = tid >> 5, t = tid & 31;    // k16 step 0..3
            int g = t >> 2, t4 = t & 3;
            int k0 = 16 * ks + 2 * t4;
            uint4 o;
            o.x = pk2(b2n_val(R, g,     k0),     b2n_val(R, g,     k0 + 1));
            o.y = pk2(b2n_val(R, g + 8, k0),     b2n_val(R, g + 8, k0 + 1));
            o.z = pk2(b2n_val(R, g,     k0 + 8), b2n_val(R, g,     k0 + 9));
            o.w = pk2(b2n_val(R, g + 8, k0 + 8), b2n_val(R, g + 8, k0 + 9));
            g_B2a[(R - 1) * 128 + ks * 32 + t] = o;
        }
    }
}

// ============================================================
// Main fused kernel: 8 signals / CTA, 128 threads (4 warps), 4 CTAs/SM.
// ============================================================
__global__ void __launch_bounds__(THREADS, 4)
dst_fused_kernel(const float* __restrict__ x, float* __restrict__ y) {
    extern __shared__ char smem[];
    const uint32_t sb = smem_u32(smem);
    const int tid  = threadIdx.x;
    const int wid  = tid >> 5;          // 0..3
    const int lane = tid & 31;
    const size_t s_base = (size_t)blockIdx.x * SIGS;

    // ---- W A-fragments -> regs (L2-hot ldg, overlaps x loads) ----
    uint4 Wf[8];
    {
        const uint4* p = g_Wf + lane;
        #pragma unroll
        for (int f = 0; f < 8; f++) Wf[f] = __ldg(p + f * 32);
    }

    // ---- per-warp x load: signals 2wid, 2wid+1 (fp32 -> fp16, pitch 80) ----
    #pragma unroll
    for (int ss = 0; ss < 2; ss++) {
        const int s = 2 * wid + ss;
        const float4* xs = reinterpret_cast<const float4*>(x + (s_base + s) * 1024);
        float4 xv[8];
        #pragma unroll
        for (int i = 0; i < 8; i++) xv[i] = xs[i * 32 + lane];
        #pragma unroll
        for (int i = 0; i < 8; i++) {
            int a = 4 * i + (lane >> 3), b = 4 * (lane & 7);
            uint2 pk;
            pk.x = pk2(xv[i].x, xv[i].y);
            pk.y = pk2(xv[i].z, xv[i].w);
            *reinterpret_cast<uint2*>(smem + SM_X + s * 2560 + a * 80 + b * 2) = pk;
        }
    }

    // ---- zero P-halves of PQ rows rp=0 and rp=32 (all 8 signals, 128 words each) ----
    {
        int s = tid >> 4;               // 0..7
        int w16 = tid & 15;             // word in P half
        int u = 4 * w16;                // byte 0..60
        uint32_t off = (uint32_t)(s * 128 + (((u >> 4) ^ (s & 7)) << 4) + (u & 15));
        sts32(sb + SM_PQ + off, 0u);                     // rp = 0
        sts32(sb + SM_PQ + 32 * PQ_PITCH + off, 0u);     // rp = 32
    }

    __syncwarp();   // own x rows visible to this warp

    // ================= Stage 1: warp = 2 signals, 4 mi tiles =================
    const int g = lane >> 2, t4 = lane & 3;
    #pragma unroll
    for (int ss = 0; ss < 2; ss++) {
        const int s = 2 * wid + ss;
        uint32_t bf[2][4][2];
        #pragma unroll
        for (int ks = 0; ks < 2; ks++)
            #pragma unroll
            for (int n16 = 0; n16 < 2; n16++) {
                int a = ks * 16 + (lane & 15);
                uint32_t addr = sb + SM_X + (uint32_t)(s * 2560 + a * 80
                              + (n16 * 16 + (lane >> 4) * 8) * 2);
                uint32_t t[4];
                ldm_x4_t(t, addr);
                bf[ks][n16 * 2 + 0][0] = t[0]; bf[ks][n16 * 2 + 0][1] = t[1];
                bf[ks][n16 * 2 + 1][0] = t[2]; bf[ks][n16 * 2 + 1][1] = t[3];
            }
        #pragma unroll
        for (int mi = 0; mi < 4; mi++) {
            float acc[4][4];
            #pragma unroll
            for (int n8 = 0; n8 < 4; n8++)
                #pragma unroll
                for (int q = 0; q < 4; q++) acc[n8][q] = 0.0f;
            #pragma unroll
            for (int ks = 0; ks < 2; ks++) {
                uint32_t af[4] = { Wf[mi * 2 + ks].x, Wf[mi * 2 + ks].y,
                                   Wf[mi * 2 + ks].z, Wf[mi * 2 + ks].w };
                #pragma unroll
                for (int n8 = 0; n8 < 4; n8++)
                    mma_16816(acc[n8], af, bf[ks][n8]);
            }
            // unpredicated packed scatter: fp -> f = (fp==63)?65:fp+1
            #pragma unroll
            for (int n8 = 0; n8 < 4; n8++)
                #pragma unroll
                for (int ch = 0; ch < 2; ch++) {
                    int fp = mi * 16 + g + (ch << 3);
                    int f  = (fp == 63) ? 65 : fp + 1;
                    int b  = n8 * 8 + 2 * t4;        // even
                    int rp = f >> 1, pq = f & 1;
                    int u  = pq * 64 + 2 * b;        // byte offset, 4-aligned
                    uint32_t addr = sb + SM_PQ + (uint32_t)(rp * PQ_PITCH + s * 128
                                  + (((u >> 4) ^ (s & 7)) << 4) + (u & 15));
                    sts32(addr, pk2(acc[n8][2 * ch], acc[n8][2 * ch + 1]));
                }
        }
    }

    // prefetch first residue's A (basis) fragments
    uint4 Ac[4];
    {
        const uint4* p = g_B2a + (size_t)(16 * wid) * 128 + lane;
        Ac[0] = __ldg(p);      Ac[1] = __ldg(p + 32);
        Ac[2] = __ldg(p + 64); Ac[3] = __ldg(p + 96);
    }

    __syncthreads();   // PQ complete; x buffer dead -> y staging (fp16 chunks)

    // ================= Stage 2 (flipped): residues R = 16*wid+1 .. 16*wid+16 =================
    // A = basis[R] (m16 = 16 c-values), B = PQ^T (n8 = signals), k = 64.
    // B via 2 non-trans ldm_x4: lane -> row s = lane&7, q-octet = lane>>3 (+4).
    const uint32_t boct0 = (uint32_t)(((lane >> 3) ^ (lane & 7)) << 4);
    const uint32_t boct1 = (uint32_t)((((lane >> 3) + 4) ^ (lane & 7)) << 4);
    const uint32_t brow  = (uint32_t)((lane & 7) * 128);

    #pragma unroll
    for (int rr = 0; rr < 2; rr++) {
        float acc[8][4];
        #pragma unroll
        for (int e = 0; e < 8; e++)
            #pragma unroll
            for (int q = 0; q < 4; q++) acc[e][q] = 0.0f;

        #pragma unroll
        for (int e = 0; e < 8; e++) {
            int idx = rr * 8 + e;               // 0..15
            int R   = 16 * wid + idx + 1;
            int rp  = (R <= 32) ? R : 64 - R;

            // B: PQ^T fragments (k64 via 2 ldm_x4)
            uint32_t bq[8];
            uint32_t pqb = sb + SM_PQ + (uint32_t)(rp * PQ_PITCH) + brow;
            ldm_x4(bq,     pqb + boct0);
            ldm_x4(bq + 4, pqb + boct1);

            // prefetch next residue's A
            uint4 An[4];
            if (idx < 15) {
                const uint4* p = g_B2a + (size_t)(16 * wid + idx + 1) * 128 + lane;
                An[0] = __ldg(p);      An[1] = __ldg(p + 32);
                An[2] = __ldg(p + 64); An[3] = __ldg(p + 96);
            }

            {
                uint32_t a0[4] = { Ac[0].x, Ac[0].y, Ac[0].z, Ac[0].w };
                mma_16816(acc[e], a0, bq);
                uint32_t a1[4] = { Ac[1].x, Ac[1].y, Ac[1].z, Ac[1].w };
                mma_16816(acc[e], a1, bq + 2);
                uint32_t a2[4] = { Ac[2].x, Ac[2].y, Ac[2].z, Ac[2].w };
                mma_16816(acc[e], a2, bq + 4);
                uint32_t a3[4] = { Ac[3].x, Ac[3].y, Ac[3].z, Ac[3].w };
                mma_16816(acc[e], a3, bq + 6);
            }
            if (idx < 15) {
                Ac[0] = An[0]; Ac[1] = An[1]; Ac[2] = An[2]; Ac[3] = An[3];
            }
        }

        // pack + store: lane (g,t4) holds y[s=2t4+sc][m = 64*(g+8gi) + R].
        // For fixed (s, grow): 8 residues = 8 consecutive M -> one sts128.
        #pragma unroll
        for (int gi = 0; gi < 2; gi++)
            #pragma unroll
            for (int sc = 0; sc < 2; sc++) {
                int cc   = gi * 2 + sc;
                int grow = g + 8 * gi;
                int s    = 2 * t4 + sc;
                uint32_t L = (uint32_t)(8 * grow + 2 * wid + rr);
                uint32_t phys = L ^ (uint32_t)(s & 7) ^ ((L >> 3) & 7u);
                sts128(sb + SM_X + (uint32_t)(s * 2048) + phys * 16,
                       pk2(acc[0][cc], acc[1][cc]), pk2(acc[2][cc], acc[3][cc]),
                       pk2(acc[4][cc], acc[5][cc]), pk2(acc[6][cc], acc[7][cc]));
            }
    }

    __syncthreads();

    // ---- copy-out: fp16 staging -> fp32 gmem, fully coalesced ----
    #pragma unroll
    for (int i = 0; i < 16; i++) {
        int flat = i * THREADS + tid;           // 0..2047 float4 index
        int s  = flat >> 8;
        int f4 = flat & 255;
        uint32_t L = (uint32_t)(f4 >> 1);
        uint32_t half = (uint32_t)(f4 & 1);
        uint32_t phys = L ^ (uint32_t)(s & 7) ^ ((L >> 3) & 7u);
        uint32_t lo, hi;
        lds64(sb + SM_X + (uint32_t)(s * 2048) + phys * 16 + half * 8, lo, hi);
        __half2 hl = *reinterpret_cast<__half2*>(&lo);
        __half2 hh = *reinterpret_cast<__half2*>(&hi);
        float2 f0 = __half22float2(hl);
        float2 f1 = __half22float2(hh);
        float4 v = make_float4(f0.x, f0.y, f1.x, f1.y);
        *reinterpret_cast<float4*>(y + (s_base + s) * 1024 + f4 * 4) = v;
    }
}

// ============================================================
// Launch
// ============================================================
extern "C" void kernel_launch(void* const* d_in, const int* in_sizes, int n_in,
                              void* d_out, int out_size) {
    const float* x = (const float*)d_in[0];
    float* y = (float*)d_out;

    build_basis_kernel<<<65, 512>>>();

    cudaFuncSetAttribute(dst_fused_kernel,
                         cudaFuncAttributeMaxDynamicSharedMemorySize, SMEM_TOTAL);
    dst_fused_kernel<<<BATCH / SIGS, THREADS, SMEM_TOTAL>>>(x, y);
}

// round 13
// speedup vs baseline: 1.1229x; 1.0499x over previous
#include <cuda_runtime.h>
#include <cuda_fp16.h>
#include <cstdint>

// ============================================================
// DST-II y[16384,1024], 3-level Cooley-Tukey:
//  Stage1: P/Q[rp][b] = sum_a x[32a+b]*{sin,cos}(pi a rp/32)
//  Stage2 (rank-factored): m = 64c+R, trig((2b+1)m) = A(c,b)*beta(R,b):
//    V1 = Q*cB - sgn*P*sB ; V2 = Q*sB + sgn*P*cB   (fp16x2 FMA on B-frags)
//    y[64c+R, s] = sum_b sinA(c,b)*V1 + cosA(c,b)*V2  (one R-indep A-table)
// R13: A-table loaded once/warp; beta 16KB L1-hot, 1-wf dedup loads.
// ============================================================

#define BATCH   16384
#define SIGS    8
#define THREADS 128
#define PQ_PITCH 1040

// smem layout (bytes)
#define SM_X    0          // x: [s8][a32][b32] fp16 pitch 80 = 20480 B; later y-staging fp16
#define SM_PQ   20480      // [rp33]{[s8] rows of 128B, XOR-chunk swizzle}, pitch 1040
#define SMEM_TOTAL (SM_PQ + 33 * PQ_PITCH)   // 54800

// gmem scratch (pre-packed fragments / tables)
__device__ uint4 g_Wf[4 * 2 * 32];   // stage-1 W A-fragments
__device__ uint4 g_A3[4 * 32];       // stage-2 A-table fragments [ks4][lane32]
__device__ uint4 g_beta[64 * 16];    // [R-1][tbl4][t4
                                     //  tbl: 0=cB 1=-sgn*sB 2=sB 3=sgn*cB

// ---------------- helpers ----------------
__device__ __forceinline__ uint32_t smem_u32(const void* p) {
    uint32_t a;
    asm("{ .reg .u64 t; cvta.to.shared.u64 t, %1; cvt.u32.u64 %0, t; }" : "=r"(a) : "l"(p));
    return a;
}
__device__ __forceinline__ void ldm_x4(uint32_t* r, uint32_t addr) {
    asm volatile("ldmatrix.sync.aligned.m8n8.x4.shared.b16 {%0,%1,%2,%3}, [%4];\n"
                 : "=r"(r[0]), "=r"(r[1]), "=r"(r[2]), "=r"(r[3]) : "r"(addr));
}
__device__ __forceinline__ void ldm_x4_t(uint32_t* r, uint32_t addr) {
    asm volatile("ldmatrix.sync.aligned.m8n8.x4.trans.shared.b16 {%0,%1,%2,%3}, [%4];\n"
                 : "=r"(r[0]), "=r"(r[1]), "=r"(r[2]), "=r"(r[3]) : "r"(addr));
}
__device__ __forceinline__ void mma_16816(float* c, const uint32_t* a, const uint32_t* b) {
    asm volatile(
        "mma.sync.aligned.m16n8k16.row.col.f32.f16.f16.f32 "
        "{%0,%1,%2,%3}, {%4,%5,%6,%7}, {%8,%9}, {%0,%1,%2,%3};\n"
        : "+f"(c[0]), "+f"(c[1]), "+f"(c[2]), "+f"(c[3])
        : "r"(a[0]), "r"(a[1]), "r"(a[2]), "r"(a[3]), "r"(b[0]), "r"(b[1]));
}
__device__ __forceinline__ void sts32(uint32_t addr, uint32_t v) {
    asm volatile("st.shared.b32 [%0], %1;\n" :: "r"(addr), "r"(v));
}
__device__ __forceinline__ void sts128(uint32_t addr, uint32_t a, uint32_t b,
                                       uint32_t c, uint32_t d) {
    asm volatile("st.shared.v4.b32 [%0], {%1,%2,%3,%4};\n"
                 :: "r"(addr), "r"(a), "r"(b), "r"(c), "r"(d));
}
__device__ __forceinline__ void lds64(uint32_t addr, uint32_t& lo, uint32_t& hi) {
    asm volatile("ld.shared.v2.b32 {%0,%1}, [%2];\n" : "=r"(lo), "=r"(hi) : "r"(addr));
}
__device__ __forceinline__ uint32_t pk2(float a, float b) {
    __half2 h = __floats2half2_rn(a, b);
    return *reinterpret_cast<uint32_t*>(&h);
}
__device__ __forceinline__ __half2 h2(uint32_t u) { return *reinterpret_cast<__half2*>(&u); }
__device__ __forceinline__ uint32_t u32(__half2 h) { return *reinterpret_cast<uint32_t*>(&h); }

// ============================================================
// Basis values
// ============================================================
__device__ __forceinline__ float w_val(int f, int a) {  // f = 2rp+pq
    int rp = f >> 1, pq = f & 1;
    if (rp > 32) return 0.0f;
    int mm = pq ? ((a * rp + 16) & 63) : ((a * rp) & 63);
    return sinpif((float)mm * (1.0f / 32.0f));
}
__device__ __forceinline__ float w2_val(int fp, int a) {
    int f = (fp == 63) ? 65 : fp + 1;
    return w_val(f, a);
}
// stage-2 A-table: k' = v*32 + b; v=0 -> sin(c(2b+1)pi/32), v=1 -> cos
__device__ __forceinline__ float a3_val(int c, int kp) {
    int v = kp >> 5, b = kp & 31;
    int ang = (c * (2 * b + 1) + (v ? 16 : 0)) & 63;
    return sinpif((float)ang * (1.0f / 32.0f));
}
// beta tables
__device__ __forceinline__ float beta_val(int R, int tbl, int b) {
    int angB = ((2 * b + 1) * R) & 4095;
    float sB = sinpif((float)angB * (1.0f / 2048.0f));
    float cB = sinpif((float)((angB + 1024) & 4095) * (1.0f / 2048.0f));
    float sgn = (R <= 32) ? 1.0f : -1.0f;
    switch (tbl) {
        case 0:  return cB;
        case 1:  return -sgn * sB;
        case 2:  return sB;
        default: return sgn * cB;
    }
}

__global__ void build_basis_kernel() {
    int bid = blockIdx.x;
    int tid = threadIdx.x;
    if (bid == 0) {
        if (tid < 256) {                 // W fragments
            int mi = tid >> 6, ks = (tid >> 5) & 1, l = tid & 31;
            int r0 = l >> 2, k0 = 16 * ks + 2 * (l & 3);
            uint4 o;
            o.x = pk2(w2_val(mi * 16 + r0,     k0),     w2_val(mi * 16 + r0,     k0 + 1));
            o.y = pk2(w2_val(mi * 16 + 8 + r0, k0),     w2_val(mi * 16 + 8 + r0, k0 + 1));
            o.z = pk2(w2_val(mi * 16 + r0,     k0 + 8), w2_val(mi * 16 + r0,     k0 + 9));
            o.w = pk2(w2_val(mi * 16 + 8 + r0, k0 + 8), w2_val(mi * 16 + 8 + r0, k0 + 9));
            g_Wf[(mi * 2 + ks) * 32 + l] = o;
        } else if (tid < 384) {          // A3 fragments
            int idx = tid - 256;
            int ks = idx >> 5, l = idx & 31;
            int g = l >> 2, t4 = l & 3;
            int k0 = 16 * ks + 2 * t4;
            uint4 o;
            o.x = pk2(a3_val(g,     k0),     a3_val(g,     k0 + 1));
            o.y = pk2(a3_val(g + 8, k0),     a3_val(g + 8, k0 + 1));
            o.z = pk2(a3_val(g,     k0 + 8), a3_val(g,     k0 + 9));
            o.w = pk2(a3_val(g + 8, k0 + 8), a3_val(g + 8, k0 + 9));
            g_A3[ks * 32 + l] = o;
        }
    } else {
        int R = bid;                     // residue 1..64
        if (tid < 16) {
            int tbl = tid >> 2, t4 = tid & 3;
            uint4 o;
            o.x = pk2(beta_val(R, tbl, 2 * t4),      beta_val(R, tbl, 2 * t4 + 1));
            o.y = pk2(beta_val(R, tbl, 8 + 2 * t4),  beta_val(R, tbl, 9 + 2 * t4));
            o.z = pk2(beta_val(R, tbl, 16 + 2 * t4), beta_val(R, tbl, 17 + 2 * t4));
            o.w = pk2(beta_val(R, tbl, 24 + 2 * t4), beta_val(R, tbl, 25 + 2 * t4));
            g_beta[(R - 1) * 16 + tbl * 4 + t4] = o;
        }
    }
}

// ============================================================
// Main fused kernel: 8 signals / CTA, 128 threads (4 warps), 4 CTAs/SM.
// ============================================================
__global__ void __launch_bounds__(THREADS, 4)
dst_fused_kernel(const float* __restrict__ x, float* __restrict__ y) {
    extern __shared__ char smem[];
    const uint32_t sb = smem_u32(smem);
    const int tid  = threadIdx.x;
    const int wid  = tid >> 5;          // 0..3
    const int lane = tid & 31;
    const size_t s_base = (size_t)blockIdx.x * SIGS;

    // ---- W A-fragments -> regs (L2-hot ldg, overlaps x loads) ----
    uint4 Wf[8];
    {
        const uint4* p = g_Wf + lane;
        #pragma unroll
        for (int f = 0; f < 8; f++) Wf[f] = __ldg(p + f * 32);
    }

    // ---- per-warp x load: signals 2wid, 2wid+1 (fp32 -> fp16, pitch 80) ----
    #pragma unroll
    for (int ss = 0; ss < 2; ss++) {
        const int s = 2 * wid + ss;
        const float4* xs = reinterpret_cast<const float4*>(x + (s_base + s) * 1024);
        float4 xv[8];
        #pragma unroll
        for (int i = 0; i < 8; i++) xv[i] = xs[i * 32 + lane];
        #pragma unroll
        for (int i = 0; i < 8; i++) {
            int a = 4 * i + (lane >> 3), b = 4 * (lane & 7);
            uint2 pk;
            pk.x = pk2(xv[i].x, xv[i].y);
            pk.y = pk2(xv[i].z, xv[i].w);
            *reinterpret_cast<uint2*>(smem + SM_X + s * 2560 + a * 80 + b * 2) = pk;
        }
    }

    // ---- zero P-halves of PQ rows rp=0 and rp=32 (all 8 signals) ----
    {
        int s = tid >> 4;               // 0..7
        int w16 = tid & 15;
        int u = 4 * w16;
        uint32_t off = (uint32_t)(s * 128 + (((u >> 4) ^ (s & 7)) << 4) + (u & 15));
        sts32(sb + SM_PQ + off, 0u);                     // rp = 0
        sts32(sb + SM_PQ + 32 * PQ_PITCH + off, 0u);     // rp = 32
    }

    __syncwarp();   // own x rows visible to this warp

    // ================= Stage 1: warp = 2 signals, 4 mi tiles =================
    const int g = lane >> 2, t4 = lane & 3;
    #pragma unroll
    for (int ss = 0; ss < 2; ss++) {
        const int s = 2 * wid + ss;
        uint32_t bf[2][4][2];
        #pragma unroll
        for (int ks = 0; ks < 2; ks++)
            #pragma unroll
            for (int n16 = 0; n16 < 2; n16++) {
                int a = ks * 16 + (lane & 15);
                uint32_t addr = sb + SM_X + (uint32_t)(s * 2560 + a * 80
                              + (n16 * 16 + (lane >> 4) * 8) * 2);
                uint32_t t[4];
                ldm_x4_t(t, addr);
                bf[ks][n16 * 2 + 0][0] = t[0]; bf[ks][n16 * 2 + 0][1] = t[1];
                bf[ks][n16 * 2 + 1][0] = t[2]; bf[ks][n16 * 2 + 1][1] = t[3];
            }
        #pragma unroll
        for (int mi = 0; mi < 4; mi++) {
            float acc[4][4];
            #pragma unroll
            for (int n8 = 0; n8 < 4; n8++)
                #pragma unroll
                for (int q = 0; q < 4; q++) acc[n8][q] = 0.0f;
            #pragma unroll
            for (int ks = 0; ks < 2; ks++) {
                uint32_t af[4] = { Wf[mi * 2 + ks].x, Wf[mi * 2 + ks].y,
                                   Wf[mi * 2 + ks].z, Wf[mi * 2 + ks].w };
                #pragma unroll
                for (int n8 = 0; n8 < 4; n8++)
                    mma_16816(acc[n8], af, bf[ks][n8]);
            }
            #pragma unroll
            for (int n8 = 0; n8 < 4; n8++)
                #pragma unroll
                for (int ch = 0; ch < 2; ch++) {
                    int fp = mi * 16 + g + (ch << 3);
                    int f  = (fp == 63) ? 65 : fp + 1;
                    int b  = n8 * 8 + 2 * t4;
                    int rp = f >> 1, pq = f & 1;
                    int u  = pq * 64 + 2 * b;
                    uint32_t addr = sb + SM_PQ + (uint32_t)(rp * PQ_PITCH + s * 128
                                  + (((u >> 4) ^ (s & 7)) << 4) + (u & 15));
                    sts32(addr, pk2(acc[n8][2 * ch], acc[n8][2 * ch + 1]));
                }
        }
    }

    // ---- A3 table fragments -> regs (once; overlaps PQ barrier) ----
    uint4 A3[4];
    {
        const uint4* p = g_A3 + lane;
        A3[0] = __ldg(p);      A3[1] = __ldg(p + 32);
        A3[2] = __ldg(p + 64); A3[3] = __ldg(p + 96);
    }

    __syncthreads();   // PQ complete; x buffer dead -> y staging (fp16 chunks)

    // ================= Stage 2: residues R = 16*wid+1 .. 16*wid+16 =================
    const uint32_t boct0 = (uint32_t)(((lane >> 3) ^ (lane & 7)) << 4);
    const uint32_t boct1 = (uint32_t)((((lane >> 3) + 4) ^ (lane & 7)) << 4);
    const uint32_t brow  = (uint32_t)((lane & 7) * 128);

    #pragma unroll
    for (int rr = 0; rr < 2; rr++) {
        float acc[8][4];
        #pragma unroll
        for (int e = 0; e < 8; e++)
            #pragma unroll
            for (int q = 0; q < 4; q++) acc[e][q] = 0.0f;

        #pragma unroll
        for (int e = 0; e < 8; e++) {
            int idx = rr * 8 + e;
            int R   = 16 * wid + idx + 1;
            int rp  = (R <= 32) ? R : 64 - R;

            // B: PQ^T fragments: bq[0..3] = P chunks, bq[4..7] = Q chunks
            uint32_t bq[8];
            uint32_t pqb = sb + SM_PQ + (uint32_t)(rp * PQ_PITCH) + brow;
            ldm_x4(bq,     pqb + boct0);
            ldm_x4(bq + 4, pqb + boct1);

            // beta tables (t4-indexed, 8-way lane dedup -> 1 wf each)
            const uint4* bp = g_beta + (size_t)(R - 1) * 16 + t4;
            uint4 cB   = __ldg(bp);
            uint4 nsBp = __ldg(bp + 4);
            uint4 sB   = __ldg(bp + 8);
            uint4 cBp  = __ldg(bp + 12);

            // V fragments: v[2j],v[2j+1] = k'-chunk j
            uint32_t v[8];
            v[0] = u32(__hfma2(h2(bq[0]), h2(nsBp.x), __hmul2(h2(bq[4]), h2(cB.x))));
            v[1] = u32(__hfma2(h2(bq[1]), h2(nsBp.y), __hmul2(h2(bq[5]), h2(cB.y))));
            v[2] = u32(__hfma2(h2(bq[2]), h2(nsBp.z), __hmul2(h2(bq[6]), h2(cB.z))));
            v[3] = u32(__hfma2(h2(bq[3]), h2(nsBp.w), __hmul2(h2(bq[7]), h2(cB.w))));
            v[4] = u32(__hfma2(h2(bq[0]), h2(cBp.x),  __hmul2(h2(bq[4]), h2(sB.x))));
            v[5] = u32(__hfma2(h2(bq[1]), h2(cBp.y),  __hmul2(h2(bq[5]), h2(sB.y))));
            v[6] = u32(__hfma2(h2(bq[2]), h2(cBp.z),  __hmul2(h2(bq[6]), h2(sB.z))));
            v[7] = u32(__hfma2(h2(bq[3]), h2(cBp.w),  __hmul2(h2(bq[7]), h2(sB.w))));

            {
                uint32_t a0[4] = { A3[0].x, A3[0].y, A3[0].z, A3[0].w };
                mma_16816(acc[e], a0, v);
                uint32_t a1[4] = { A3[1].x, A3[1].y, A3[1].z, A3[1].w };
                mma_16816(acc[e], a1, v + 2);
                uint32_t a2[4] = { A3[2].x, A3[2].y, A3[2].z, A3[2].w };
                mma_16816(acc[e], a2, v + 4);
                uint32_t a3[4] = { A3[3].x, A3[3].y, A3[3].z, A3[3].w };
                mma_16816(acc[e], a3, v + 6);
            }
        }

        // pack + store: lane (g,t4) holds y[s=2t4+sc][m = 64*(g+8gi) + R]
        #pragma unroll
        for (int gi = 0; gi < 2; gi++)
            #pragma unroll
            for (int sc = 0; sc < 2; sc++) {
                int cc   = gi * 2 + sc;
                int grow = g + 8 * gi;
                int s    = 2 * t4 + sc;
                uint32_t L = (uint32_t)(8 * grow + 2 * wid + rr);
                uint32_t phys = L ^ (uint32_t)(s & 7) ^ ((L >> 3) & 7u);
                sts128(sb + SM_X + (uint32_t)(s * 2048) + phys * 16,
                       pk2(acc[0][cc], acc[1][cc]), pk2(acc[2][cc], acc[3][cc]),
                       pk2(acc[4][cc], acc[5][cc]), pk2(acc[6][cc], acc[7][cc]));
            }
    }

    __syncthreads();

    // ---- copy-out: fp16 staging -> fp32 gmem, fully coalesced ----
    #pragma unroll
    for (int i = 0; i < 16; i++) {
        int flat = i * THREADS + tid;
        int s  = flat >> 8;
        int f4 = flat & 255;
        uint32_t L = (uint32_t)(f4 >> 1);
        uint32_t half = (uint32_t)(f4 & 1);
        uint32_t phys = L ^ (uint32_t)(s & 7) ^ ((L >> 3) & 7u);
        uint32_t lo, hi;
        lds64(sb + SM_X + (uint32_t)(s * 2048) + phys * 16 + half * 8, lo, hi);
        __half2 hl = h2(lo);
        __half2 hh = h2(hi);
        float2 f0 = __half22float2(hl);
        float2 f1 = __half22float2(hh);
        float4 v = make_float4(f0.x, f0.y, f1.x, f1.y);
        *reinterpret_cast<float4*>(y + (s_base + s) * 1024 + f4 * 4) = v;
    }
}

// ============================================================
// Launch
// ============================================================
extern "C" void kernel_launch(void* const* d_in, const int* in_sizes, int n_in,
                              void* d_out, int out_size) {
    const float* x = (const float*)d_in[0];
    float* y = (float*)d_out;

    build_basis_kernel<<<65, 512>>>();

    cudaFuncSetAttribute(dst_fused_kernel,
                         cudaFuncAttributeMaxDynamicSharedMemorySize, SMEM_TOTAL);
    dst_fused_kernel<<<BATCH / SIGS, THREADS, SMEM_TOTAL>>>(x, y);
}

// round 14
// speedup vs baseline: 1.1237x; 1.0007x over previous
#include <cuda_runtime.h>
#include <cuda_fp16.h>
#include <cstdint>

// ============================================================
// DST-II y[16384,1024], 3-level Cooley-Tukey:
//  Stage1: P/Q[rp][b] = sum_a x[32a+b]*{sin,cos}(pi a rp/32)
//  Stage2 (rank-factored): m = 64c+R, V1 = Q*cB - sgn*P*sB,
//    V2 = Q*sB + sgn*P*cB; y = sum_b sinA*V1 + cosA*V2.
// R14: mirror-rp pairing — warp w owns A: R=8w+1..8w+8 and
//      B: R=57-8w..64-8w; rp union = 9 rows -> PQ ldsm 32 -> 18.
// ============================================================

#define BATCH   16384
#define SIGS    8
#define THREADS 128
#define PQ_PITCH 1040

// smem layout (bytes)
#define SM_X    0          // x: [s8][a32][b32] fp16 pitch 80 = 20480 B; later y-staging fp16
#define SM_PQ   20480      // [rp33]{[s8] rows of 128B, XOR-chunk swizzle}, pitch 1040
#define SMEM_TOTAL (SM_PQ + 33 * PQ_PITCH)   // 54800

// gmem scratch (pre-packed fragments / tables)
__device__ uint4 g_Wf[4 * 2 * 32];   // stage-1 W A-fragments
__device__ uint4 g_A3[4 * 32];       // stage-2 A-table fragments [ks4][lane32]
__device__ uint4 g_beta[64 * 16];    // [R-1][tbl4][t4]; tbl: 0=cB 1=-sgn*sB 2=sB 3=sgn*cB

// ---------------- helpers ----------------
__device__ __forceinline__ uint32_t smem_u32(const void* p) {
    uint32_t a;
    asm("{ .reg .u64 t; cvta.to.shared.u64 t, %1; cvt.u32.u64 %0, t; }" : "=r"(a) : "l"(p));
    return a;
}
__device__ __forceinline__ void ldm_x4(uint32_t* r, uint32_t addr) {
    asm volatile("ldmatrix.sync.aligned.m8n8.x4.shared.b16 {%0,%1,%2,%3}, [%4];\n"
                 : "=r"(r[0]), "=r"(r[1]), "=r"(r[2]), "=r"(r[3]) : "r"(addr));
}
__device__ __forceinline__ void ldm_x4_t(uint32_t* r, uint32_t addr) {
    asm volatile("ldmatrix.sync.aligned.m8n8.x4.trans.shared.b16 {%0,%1,%2,%3}, [%4];\n"
                 : "=r"(r[0]), "=r"(r[1]), "=r"(r[2]), "=r"(r[3]) : "r"(addr));
}
__device__ __forceinline__ void mma_16816(float* c, const uint32_t* a, const uint32_t* b) {
    asm volatile(
        "mma.sync.aligned.m16n8k16.row.col.f32.f16.f16.f32 "
        "{%0,%1,%2,%3}, {%4,%5,%6,%7}, {%8,%9}, {%0,%1,%2,%3};\n"
        : "+f"(c[0]), "+f"(c[1]), "+f"(c[2]), "+f"(c[3])
        : "r"(a[0]), "r"(a[1]), "r"(a[2]), "r"(a[3]), "r"(b[0]), "r"(b[1]));
}
__device__ __forceinline__ void sts32(uint32_t addr, uint32_t v) {
    asm volatile("st.shared.b32 [%0], %1;\n" :: "r"(addr), "r"(v));
}
__device__ __forceinline__ void sts128(uint32_t addr, uint32_t a, uint32_t b,
                                       uint32_t c, uint32_t d) {
    asm volatile("st.shared.v4.b32 [%0], {%1,%2,%3,%4};\n"
                 :: "r"(addr), "r"(a), "r"(b), "r"(c), "r"(d));
}
__device__ __forceinline__ void lds64(uint32_t addr, uint32_t& lo, uint32_t& hi) {
    asm volatile("ld.shared.v2.b32 {%0,%1}, [%2];\n" : "=r"(lo), "=r"(hi) : "r"(addr));
}
__device__ __forceinline__ uint32_t pk2(float a, float b) {
    __half2 h = __floats2half2_rn(a, b);
    return *reinterpret_cast<uint32_t*>(&h);
}
__device__ __forceinline__ __half2 h2(uint32_t u) { return *reinterpret_cast<__half2*>(&u); }
__device__ __forceinline__ uint32_t u32(__half2 h) { return *reinterpret_cast<uint32_t*>(&h); }

// ============================================================
// Basis values
// ============================================================
__device__ __forceinline__ float w_val(int f, int a) {  // f = 2rp+pq
    int rp = f >> 1, pq = f & 1;
    if (rp > 32) return 0.0f;
    int mm = pq ? ((a * rp + 16) & 63) : ((a * rp) & 63);
    return sinpif((float)mm * (1.0f / 32.0f));
}
__device__ __forceinline__ float w2_val(int fp, int a) {
    int f = (fp == 63) ? 65 : fp + 1;
    return w_val(f, a);
}
// stage-2 A-table: k' = v*32 + b; v=0 -> sin(c(2b+1)pi/32), v=1 -> cos
__device__ __forceinline__ float a3_val(int c, int kp) {
    int v = kp >> 5, b = kp & 31;
    int ang = (c * (2 * b + 1) + (v ? 16 : 0)) & 63;
    return sinpif((float)ang * (1.0f / 32.0f));
}
// beta tables
__device__ __forceinline__ float beta_val(int R, int tbl, int b) {
    int angB = ((2 * b + 1) * R) & 4095;
    float sB = sinpif((float)angB * (1.0f / 2048.0f));
    float cB = sinpif((float)((angB + 1024) & 4095) * (1.0f / 2048.0f));
    float sgn = (R <= 32) ? 1.0f : -1.0f;
    switch (tbl) {
        case 0:  return cB;
        case 1:  return -sgn * sB;
        case 2:  return sB;
        default: return sgn * cB;
    }
}

__global__ void build_basis_kernel() {
    int bid = blockIdx.x;
    int tid = threadIdx.x;
    if (bid == 0) {
        if (tid < 256) {                 // W fragments
            int mi = tid >> 6, ks = (tid >> 5) & 1, l = tid & 31;
            int r0 = l >> 2, k0 = 16 * ks + 2 * (l & 3);
            uint4 o;
            o.x = pk2(w2_val(mi * 16 + r0,     k0),     w2_val(mi * 16 + r0,     k0 + 1));
            o.y = pk2(w2_val(mi * 16 + 8 + r0, k0),     w2_val(mi * 16 + 8 + r0, k0 + 1));
            o.z = pk2(w2_val(mi * 16 + r0,     k0 + 8), w2_val(mi * 16 + r0,     k0 + 9));
            o.w = pk2(w2_val(mi * 16 + 8 + r0, k0 + 8), w2_val(mi * 16 + 8 + r0, k0 + 9));
            g_Wf[(mi * 2 + ks) * 32 + l] = o;
        } else if (tid < 384) {          // A3 fragments
            int idx = tid - 256;
            int ks = idx >> 5, l = idx & 31;
            int g = l >> 2, t4 = l & 3;
            int k0 = 16 * ks + 2 * t4;
            uint4 o;
            o.x = pk2(a3_val(g,     k0),     a3_val(g,     k0 + 1));
            o.y = pk2(a3_val(g + 8, k0),     a3_val(g + 8, k0 + 1));
            o.z = pk2(a3_val(g,     k0 + 8), a3_val(g,     k0 + 9));
            o.w = pk2(a3_val(g + 8, k0 + 8), a3_val(g + 8, k0 + 9));
            g_A3[ks * 32 + l] = o;
        }
    } else {
        int R = bid;                     // residue 1..64
        if (tid < 16) {
            int tbl = tid >> 2, t4 = tid & 3;
            uint4 o;
            o.x = pk2(beta_val(R, tbl, 2 * t4),      beta_val(R, tbl, 2 * t4 + 1));
            o.y = pk2(beta_val(R, tbl, 8 + 2 * t4),  beta_val(R, tbl, 9 + 2 * t4));
            o.z = pk2(beta_val(R, tbl, 16 + 2 * t4), beta_val(R, tbl, 17 + 2 * t4));
            o.w = pk2(beta_val(R, tbl, 24 + 2 * t4), beta_val(R, tbl, 25 + 2 * t4));
            g_beta[(R - 1) * 16 + tbl * 4 + t4] = o;
        }
    }
}

// ============================================================
// Per-residue V + MMA worker: acc += [A_sin,A_cos] . V(beta(R), bq)
// ============================================================
__device__ __forceinline__ void residue_mma(float* acc, const uint32_t* bq,
                                            const uint4* A3, int R, int t4) {
    const uint4* bp = g_beta + (size_t)(R - 1) * 16 + t4;
    uint32_t v[8];
    {   // V1 = P*(-sgn sB) + Q*cB
        uint4 cB   = __ldg(bp);
        uint4 nsBp = __ldg(bp + 4);
        v[0] = u32(__hfma2(h2(bq[0]), h2(nsBp.x), __hmul2(h2(bq[4]), h2(cB.x))));
        v[1] = u32(__hfma2(h2(bq[1]), h2(nsBp.y), __hmul2(h2(bq[5]), h2(cB.y))));
        v[2] = u32(__hfma2(h2(bq[2]), h2(nsBp.z), __hmul2(h2(bq[6]), h2(cB.z))));
        v[3] = u32(__hfma2(h2(bq[3]), h2(nsBp.w), __hmul2(h2(bq[7]), h2(cB.w))));
    }
    {   // V2 = P*(sgn cB) + Q*sB
        uint4 sB  = __ldg(bp + 8);
        uint4 cBp = __ldg(bp + 12);
        v[4] = u32(__hfma2(h2(bq[0]), h2(cBp.x), __hmul2(h2(bq[4]), h2(sB.x))));
        v[5] = u32(__hfma2(h2(bq[1]), h2(cBp.y), __hmul2(h2(bq[5]), h2(sB.y))));
        v[6] = u32(__hfma2(h2(bq[2]), h2(cBp.z), __hmul2(h2(bq[6]), h2(sB.z))));
        v[7] = u32(__hfma2(h2(bq[3]), h2(cBp.w), __hmul2(h2(bq[7]), h2(sB.w))));
    }
    uint32_t a0[4] = { A3[0].x, A3[0].y, A3[0].z, A3[0].w };
    mma_16816(acc, a0, v);
    uint32_t a1[4] = { A3[1].x, A3[1].y, A3[1].z, A3[1].w };
    mma_16816(acc, a1, v + 2);
    uint32_t a2[4] = { A3[2].x, A3[2].y, A3[2].z, A3[2].w };
    mma_16816(acc, a2, v + 4);
    uint32_t a3[4] = { A3[3].x, A3[3].y, A3[3].z, A3[3].w };
    mma_16816(acc, a3, v + 6);
}

// ============================================================
// Main fused kernel: 8 signals / CTA, 128 threads (4 warps), 4 CTAs/SM.
// ============================================================
__global__ void __launch_bounds__(THREADS, 4)
dst_fused_kernel(const float* __restrict__ x, float* __restrict__ y) {
    extern __shared__ char smem[];
    const uint32_t sb = smem_u32(smem);
    const int tid  = threadIdx.x;
    const int wid  = tid >> 5;          // 0..3
    const int lane = tid & 31;
    const size_t s_base = (size_t)blockIdx.x * SIGS;

    // ---- W A-fragments -> regs ----
    uint4 Wf[8];
    {
        const uint4* p = g_Wf + lane;
        #pragma unroll
        for (int f = 0; f < 8; f++) Wf[f] = __ldg(p + f * 32);
    }

    // ---- per-warp x load: signals 2wid, 2wid+1 (fp32 -> fp16, pitch 80) ----
    #pragma unroll
    for (int ss = 0; ss < 2; ss++) {
        const int s = 2 * wid + ss;
        const float4* xs = reinterpret_cast<const float4*>(x + (s_base + s) * 1024);
        float4 xv[8];
        #pragma unroll
        for (int i = 0; i < 8; i++) xv[i] = xs[i * 32 + lane];
        #pragma unroll
        for (int i = 0; i < 8; i++) {
            int a = 4 * i + (lane >> 3), b = 4 * (lane & 7);
            uint2 pk;
            pk.x = pk2(xv[i].x, xv[i].y);
            pk.y = pk2(xv[i].z, xv[i].w);
            *reinterpret_cast<uint2*>(smem + SM_X + s * 2560 + a * 80 + b * 2) = pk;
        }
    }

    // ---- zero P-halves of PQ rows rp=0 and rp=32 (all 8 signals) ----
    {
        int s = tid >> 4;
        int w16 = tid & 15;
        int u = 4 * w16;
        uint32_t off = (uint32_t)(s * 128 + (((u >> 4) ^ (s & 7)) << 4) + (u & 15));
        sts32(sb + SM_PQ + off, 0u);
        sts32(sb + SM_PQ + 32 * PQ_PITCH + off, 0u);
    }

    __syncwarp();

    // ================= Stage 1: warp = 2 signals, 4 mi tiles =================
    const int g = lane >> 2, t4 = lane & 3;
    #pragma unroll
    for (int ss = 0; ss < 2; ss++) {
        const int s = 2 * wid + ss;
        uint32_t bf[2][4][2];
        #pragma unroll
        for (int ks = 0; ks < 2; ks++)
            #pragma unroll
            for (int n16 = 0; n16 < 2; n16++) {
                int a = ks * 16 + (lane & 15);
                uint32_t addr = sb + SM_X + (uint32_t)(s * 2560 + a * 80
                              + (n16 * 16 + (lane >> 4) * 8) * 2);
                uint32_t t[4];
                ldm_x4_t(t, addr);
                bf[ks][n16 * 2 + 0][0] = t[0]; bf[ks][n16 * 2 + 0][1] = t[1];
                bf[ks][n16 * 2 + 1][0] = t[2]; bf[ks][n16 * 2 + 1][1] = t[3];
            }
        #pragma unroll
        for (int mi = 0; mi < 4; mi++) {
            float acc[4][4];
            #pragma unroll
            for (int n8 = 0; n8 < 4; n8++)
                #pragma unroll
                for (int q = 0; q < 4; q++) acc[n8][q] = 0.0f;
            #pragma unroll
            for (int ks = 0; ks < 2; ks++) {
                uint32_t af[4] = { Wf[mi * 2 + ks].x, Wf[mi * 2 + ks].y,
                                   Wf[mi * 2 + ks].z, Wf[mi * 2 + ks].w };
                #pragma unroll
                for (int n8 = 0; n8 < 4; n8++)
                    mma_16816(acc[n8], af, bf[ks][n8]);
            }
            #pragma unroll
            for (int n8 = 0; n8 < 4; n8++)
                #pragma unroll
                for (int ch = 0; ch < 2; ch++) {
                    int fp = mi * 16 + g + (ch << 3);
                    int f  = (fp == 63) ? 65 : fp + 1;
                    int b  = n8 * 8 + 2 * t4;
                    int rp = f >> 1, pq = f & 1;
                    int u  = pq * 64 + 2 * b;
                    uint32_t addr = sb + SM_PQ + (uint32_t)(rp * PQ_PITCH + s * 128
                                  + (((u >> 4) ^ (s & 7)) << 4) + (u & 15));
                    sts32(addr, pk2(acc[n8][2 * ch], acc[n8][2 * ch + 1]));
                }
        }
    }

    // ---- A3 table fragments -> regs (once; overlaps PQ barrier) ----
    uint4 A3[4];
    {
        const uint4* p = g_A3 + lane;
        A3[0] = __ldg(p);      A3[1] = __ldg(p + 32);
        A3[2] = __ldg(p + 64); A3[3] = __ldg(p + 96);
    }

    __syncthreads();   // PQ complete; x buffer dead -> y staging (fp16 chunks)

    // ================= Stage 2: mirror-rp pairing =================
    // Warp w: A-group R = 8w+1..8w+8 (eA = R-8w-1),
    //         B-group R = 57-8w..64-8w (eB = R-(57-8w)), rp = 64-R.
    // Loop rp = 8w..8w+8: one bq load feeds A (rp>8w) and B (rp<8w+8).
    const uint32_t boct0 = (uint32_t)(((lane >> 3) ^ (lane & 7)) << 4);
    const uint32_t boct1 = (uint32_t)((((lane >> 3) + 4) ^ (lane & 7)) << 4);
    const uint32_t brow  = (uint32_t)((lane & 7) * 128);

    float accA[8][4], accB[8][4];
    #pragma unroll
    for (int e = 0; e < 8; e++)
        #pragma unroll
        for (int q = 0; q < 4; q++) { accA[e][q] = 0.0f; accB[e][q] = 0.0f; }

    #pragma unroll
    for (int i = 0; i <= 8; i++) {
        int rp = 8 * wid + i;

        uint32_t bq[8];
        uint32_t pqb = sb + SM_PQ + (uint32_t)(rp * PQ_PITCH) + brow;
        ldm_x4(bq,     pqb + boct0);
        ldm_x4(bq + 4, pqb + boct1);

        if (i > 0)   // A residue: R = rp
            residue_mma(accA[i - 1], bq, A3, rp, t4);
        if (i < 8)   // B residue: R = 64 - rp
            residue_mma(accB[7 - i], bq, A3, 64 - rp, t4);
    }

    // pack + store: lane (g,t4) holds y[s=2t4+sc][m]
    //  A: m-1 = 64*grow + 8w + e      -> chunk L = 8*grow + w
    //  B: m-1 = 64*grow + (56-8w) + e -> chunk L = 8*grow + (7-w)
    #pragma unroll
    for (int gi = 0; gi < 2; gi++)
        #pragma unroll
        for (int sc = 0; sc < 2; sc++) {
            int cc   = gi * 2 + sc;
            int grow = g + 8 * gi;
            int s    = 2 * t4 + sc;
            uint32_t LA = (uint32_t)(8 * grow + wid);
            uint32_t physA = LA ^ (uint32_t)(s & 7) ^ ((LA >> 3) & 7u);
            sts128(sb + SM_X + (uint32_t)(s * 2048) + physA * 16,
                   pk2(accA[0][cc], accA[1][cc]), pk2(accA[2][cc], accA[3][cc]),
                   pk2(accA[4][cc], accA[5][cc]), pk2(accA[6][cc], accA[7][cc]));
            uint32_t LB = (uint32_t)(8 * grow + 7 - wid);
            uint32_t physB = LB ^ (uint32_t)(s & 7) ^ ((LB >> 3) & 7u);
            sts128(sb + SM_X + (uint32_t)(s * 2048) + physB * 16,
                   pk2(accB[0][cc], accB[1][cc]), pk2(accB[2][cc], accB[3][cc]),
                   pk2(accB[4][cc], accB[5][cc]), pk2(accB[6][cc], accB[7][cc]));
        }

    __syncthreads();

    // ---- copy-out: fp16 staging -> fp32 gmem, fully coalesced ----
    #pragma unroll
    for (int i = 0; i < 16; i++) {
        int flat = i * THREADS + tid;
        int s  = flat >> 8;
        int f4 = flat & 255;
        uint32_t L = (uint32_t)(f4 >> 1);
        uint32_t half = (uint32_t)(f4 & 1);
        uint32_t phys = L ^ (uint32_t)(s & 7) ^ ((L >> 3) & 7u);
        uint32_t lo, hi;
        lds64(sb + SM_X + (uint32_t)(s * 2048) + phys * 16 + half * 8, lo, hi);
        __half2 hl = h2(lo);
        __half2 hh = h2(hi);
        float2 f0 = __half22float2(hl);
        float2 f1 = __half22float2(hh);
        float4 v = make_float4(f0.x, f0.y, f1.x, f1.y);
        *reinterpret_cast<float4*>(y + (s_base + s) * 1024 + f4 * 4) = v;
    }
}

// ============================================================
// Launch
// ============================================================
extern "C" void kernel_launch(void* const* d_in, const int* in_sizes, int n_in,
                              void* d_out, int out_size) {
    const float* x = (const float*)d_in[0];
    float* y = (float*)d_out;

    build_basis_kernel<<<65, 512>>>();

    cudaFuncSetAttribute(dst_fused_kernel,
                         cudaFuncAttributeMaxDynamicSharedMemorySize, SMEM_TOTAL);
    dst_fused_kernel<<<BATCH / SIGS, THREADS, SMEM_TOTAL>>>(x, y);
}